// round 6
// baseline (speedup 1.0000x reference)
#include <cuda_runtime.h>
#include <cuda_bf16.h>

#define NNODES 100000
#define NEDGES 1600000
#define F 128
#define SCAN_T 1024
#define NSCAN ((NNODES + SCAN_T - 1) / SCAN_T)   // 98

// ---------------- scratch (static __device__, no allocs) ----------------
__device__ int   g_deg[NNODES];
__device__ float g_invdeg[NNODES];
__device__ int   g_rowptr[NNODES + 1];
__device__ int   g_cursor[NNODES];
__device__ int   g_csrsrc[NEDGES];
__device__ int   g_partials[NSCAN];
__device__ int   g_scanbuf[NNODES];
__device__ float g_h0[NNODES * F];
__device__ float g_h1[NNODES * F];
__device__ float g_mean[NNODES * F];
__device__ float g_A[NNODES * F];
__device__ float g_B[NNODES * F];

// ---------------- CSR build ----------------
__global__ void k_zero_deg() {
    int i = blockIdx.x * blockDim.x + threadIdx.x;
    if (i < NNODES) g_deg[i] = 0;
}

__global__ void k_hist(const int* __restrict__ dst) {
    int e = blockIdx.x * blockDim.x + threadIdx.x;
    if (e < NEDGES) atomicAdd(&g_deg[dst[e]], 1);
}

__global__ void k_scan1() {
    __shared__ int sd[SCAN_T];
    int t = threadIdx.x;
    int i = blockIdx.x * SCAN_T + t;
    int v = (i < NNODES) ? g_deg[i] : 0;
    sd[t] = v;
    __syncthreads();
    for (int off = 1; off < SCAN_T; off <<= 1) {
        int add = (t >= off) ? sd[t - off] : 0;
        __syncthreads();
        sd[t] += add;
        __syncthreads();
    }
    if (i < NNODES) g_scanbuf[i] = sd[t];
    if (t == SCAN_T - 1) g_partials[blockIdx.x] = sd[t];
}

__global__ void k_scan2() {
    if (threadIdx.x == 0) {
        int run = 0;
        for (int b = 0; b < NSCAN; b++) {
            int p = g_partials[b];
            g_partials[b] = run;
            run += p;
        }
    }
}

__global__ void k_scan3() {
    int i = blockIdx.x * blockDim.x + threadIdx.x;
    if (i < NNODES) {
        int incl = g_scanbuf[i] + g_partials[i >> 10];
        int d = g_deg[i];
        int excl = incl - d;
        g_rowptr[i] = excl;
        g_cursor[i] = excl;
        g_invdeg[i] = 1.0f / fmaxf((float)d, 1.0f);
        if (i == 0) g_rowptr[NNODES] = NEDGES;
    }
}

__global__ void k_scatter(const int* __restrict__ src, const int* __restrict__ dst) {
    int e = blockIdx.x * blockDim.x + threadIdx.x;
    if (e < NEDGES) {
        int pos = atomicAdd(&g_cursor[dst[e]], 1);
        g_csrsrc[pos] = src[e];
    }
}

// ---------------- mean aggregation (one warp per dst node, 4-deep MLP) ----------------
__global__ void __launch_bounds__(256) k_aggmean(const float* __restrict__ h) {
    int w    = (blockIdx.x * blockDim.x + threadIdx.x) >> 5;
    int lane = threadIdx.x & 31;
    if (w >= NNODES) return;
    int beg = g_rowptr[w], end = g_rowptr[w + 1];
    int f0 = lane * 4;
    float4 acc = make_float4(0.f, 0.f, 0.f, 0.f);
    for (int i = beg; i < end; i += 32) {
        int n = min(32, end - i);
        int sidx = (lane < n) ? g_csrsrc[i + lane] : 0;
        int j = 0;
        for (; j + 4 <= n; j += 4) {
            int s0 = __shfl_sync(0xffffffffu, sidx, j + 0);
            int s1 = __shfl_sync(0xffffffffu, sidx, j + 1);
            int s2 = __shfl_sync(0xffffffffu, sidx, j + 2);
            int s3 = __shfl_sync(0xffffffffu, sidx, j + 3);
            float4 v0 = *reinterpret_cast<const float4*>(h + s0 * F + f0);
            float4 v1 = *reinterpret_cast<const float4*>(h + s1 * F + f0);
            float4 v2 = *reinterpret_cast<const float4*>(h + s2 * F + f0);
            float4 v3 = *reinterpret_cast<const float4*>(h + s3 * F + f0);
            acc.x += v0.x + v1.x + v2.x + v3.x;
            acc.y += v0.y + v1.y + v2.y + v3.y;
            acc.z += v0.z + v1.z + v2.z + v3.z;
            acc.w += v0.w + v1.w + v2.w + v3.w;
        }
        for (; j < n; j++) {
            int s = __shfl_sync(0xffffffffu, sidx, j);
            float4 v = *reinterpret_cast<const float4*>(h + s * F + f0);
            acc.x += v.x; acc.y += v.y; acc.z += v.z; acc.w += v.w;
        }
    }
    float sc = g_invdeg[w];
    acc.x *= sc; acc.y *= sc; acc.z *= sc; acc.w *= sc;
    *reinterpret_cast<float4*>(g_mean + w * F + f0) = acc;
}

// ---------------- tensor-core GEMM with bf16 two-term split ----------------
// out = X1@W1 (+ X2@W2) (+bias) (+leaky relu)
// Block tile: BM=128, BN=128, K handled in BK=32 chunks. 256 threads = 8 warps
// (2x4 warp grid, warp tile 64x32). Each fp32 operand is split x = x_hi + x_lo
// (both bf16); 3 mma passes: hi*hi + hi*lo + lo*hi (fp32 accumulate).

__device__ __forceinline__ void mma_bf16(float* c, const unsigned* a, const unsigned* b) {
    asm volatile(
        "mma.sync.aligned.m16n8k16.row.col.f32.bf16.bf16.f32 "
        "{%0,%1,%2,%3}, {%4,%5,%6,%7}, {%8,%9}, {%0,%1,%2,%3};"
        : "+f"(c[0]), "+f"(c[1]), "+f"(c[2]), "+f"(c[3])
        : "r"(a[0]), "r"(a[1]), "r"(a[2]), "r"(a[3]), "r"(b[0]), "r"(b[1]));
}

__device__ __forceinline__ void split_bf16(float v, __nv_bfloat16& h, __nv_bfloat16& l) {
    h = __float2bfloat16_rn(v);
    l = __float2bfloat16_rn(v - __bfloat162float(h));
}

#define SPAD 40   // bf16 row stride: 80B = 20 banks/row -> conflict-free frag loads

template <bool HAS2, bool LEAKY>
__global__ void __launch_bounds__(256) gemm_tc(
    const float* __restrict__ X1, const float* __restrict__ W1,
    const float* __restrict__ X2, const float* __restrict__ W2,
    const float* __restrict__ bias, float* __restrict__ out, int M)
{
    __shared__ alignas(16) __nv_bfloat16 sAh[128][SPAD];
    __shared__ alignas(16) __nv_bfloat16 sAl[128][SPAD];
    __shared__ alignas(16) __nv_bfloat16 sWh[128][SPAD];   // stored transposed: sW[n][k]
    __shared__ alignas(16) __nv_bfloat16 sWl[128][SPAD];

    const int tid  = threadIdx.x;
    const int lane = tid & 31;
    const int g    = lane >> 2;      // 0..7
    const int tg   = lane & 3;       // 0..3
    const int wm   = (tid >> 5) >> 2;   // 0..1
    const int wn   = (tid >> 5) & 3;    // 0..3
    const int rowBase = blockIdx.x * 128;

    float acc[4][4][4];
#pragma unroll
    for (int mt = 0; mt < 4; mt++)
#pragma unroll
        for (int nt = 0; nt < 4; nt++)
#pragma unroll
            for (int q = 0; q < 4; q++) acc[mt][nt][q] = 0.f;

    const int NCHUNK = HAS2 ? 8 : 4;
    for (int c = 0; c < NCHUNK; c++) {
        const float* Xp = (c < 4) ? X1 : X2;
        const float* Wp = (c < 4) ? W1 : W2;
        const int k0 = (c & 3) * 32;

        // ---- load & split A chunk: 128 rows x 32 k ----
#pragma unroll
        for (int e = tid; e < 1024; e += 256) {
            int row = e >> 3;
            int c4  = (e & 7) << 2;
            int grow = rowBase + row;
            float4 v = make_float4(0.f, 0.f, 0.f, 0.f);
            if (grow < M)
                v = *reinterpret_cast<const float4*>(Xp + grow * F + k0 + c4);
            __nv_bfloat16 h0, l0, h1, l1, h2, l2, h3, l3;
            split_bf16(v.x, h0, l0); split_bf16(v.y, h1, l1);
            split_bf16(v.z, h2, l2); split_bf16(v.w, h3, l3);
            *reinterpret_cast<__nv_bfloat162*>(&sAh[row][c4])     = __nv_bfloat162(h0, h1);
            *reinterpret_cast<__nv_bfloat162*>(&sAh[row][c4 + 2]) = __nv_bfloat162(h2, h3);
            *reinterpret_cast<__nv_bfloat162*>(&sAl[row][c4])     = __nv_bfloat162(l0, l1);
            *reinterpret_cast<__nv_bfloat162*>(&sAl[row][c4 + 2]) = __nv_bfloat162(l2, l3);
        }
        // ---- load & split W chunk: 32 k-rows x 128 n, store transposed [n][k] ----
#pragma unroll
        for (int e = tid; e < 1024; e += 256) {
            int k  = e >> 5;
            int n4 = (e & 31) << 2;
            float4 w = *reinterpret_cast<const float4*>(Wp + (k0 + k) * F + n4);
            float vv[4] = {w.x, w.y, w.z, w.w};
#pragma unroll
            for (int j = 0; j < 4; j++) {
                __nv_bfloat16 h, l;
                split_bf16(vv[j], h, l);
                sWh[n4 + j][k] = h;
                sWl[n4 + j][k] = l;
            }
        }
        __syncthreads();

        // ---- compute: 2 k16-steps per chunk, 3 split passes each ----
#pragma unroll
        for (int kk = 0; kk < 2; kk++) {
            const int kb = kk * 16 + tg * 2;
            unsigned bh[4][2], bl[4][2];
#pragma unroll
            for (int nt = 0; nt < 4; nt++) {
                const int n0 = wn * 32 + nt * 8 + g;
                bh[nt][0] = *reinterpret_cast<const unsigned*>(&sWh[n0][kb]);
                bh[nt][1] = *reinterpret_cast<const unsigned*>(&sWh[n0][kb + 8]);
                bl[nt][0] = *reinterpret_cast<const unsigned*>(&sWl[n0][kb]);
                bl[nt][1] = *reinterpret_cast<const unsigned*>(&sWl[n0][kb + 8]);
            }
#pragma unroll
            for (int mt = 0; mt < 4; mt++) {
                const int r0 = wm * 64 + mt * 16 + g;
                unsigned ah[4], al[4];
                ah[0] = *reinterpret_cast<const unsigned*>(&sAh[r0][kb]);
                ah[1] = *reinterpret_cast<const unsigned*>(&sAh[r0 + 8][kb]);
                ah[2] = *reinterpret_cast<const unsigned*>(&sAh[r0][kb + 8]);
                ah[3] = *reinterpret_cast<const unsigned*>(&sAh[r0 + 8][kb + 8]);
#pragma unroll
                for (int nt = 0; nt < 4; nt++) mma_bf16(acc[mt][nt], ah, bh[nt]);
#pragma unroll
                for (int nt = 0; nt < 4; nt++) mma_bf16(acc[mt][nt], ah, bl[nt]);
                al[0] = *reinterpret_cast<const unsigned*>(&sAl[r0][kb]);
                al[1] = *reinterpret_cast<const unsigned*>(&sAl[r0 + 8][kb]);
                al[2] = *reinterpret_cast<const unsigned*>(&sAl[r0][kb + 8]);
                al[3] = *reinterpret_cast<const unsigned*>(&sAl[r0 + 8][kb + 8]);
#pragma unroll
                for (int nt = 0; nt < 4; nt++) mma_bf16(acc[mt][nt], al, bh[nt]);
            }
        }
        __syncthreads();
    }

    // ---- epilogue ----
#pragma unroll
    for (int nt = 0; nt < 4; nt++) {
        const int col = wn * 32 + nt * 8 + tg * 2;
        const float b0v = bias ? bias[col]     : 0.f;
        const float b1v = bias ? bias[col + 1] : 0.f;
#pragma unroll
        for (int mt = 0; mt < 4; mt++) {
            const int r0 = rowBase + wm * 64 + mt * 16 + g;
            float v0 = acc[mt][nt][0] + b0v;
            float v1 = acc[mt][nt][1] + b1v;
            float v2 = acc[mt][nt][2] + b0v;
            float v3 = acc[mt][nt][3] + b1v;
            if (LEAKY) {
                v0 = (v0 > 0.f) ? v0 : 0.01f * v0;
                v1 = (v1 > 0.f) ? v1 : 0.01f * v1;
                v2 = (v2 > 0.f) ? v2 : 0.01f * v2;
                v3 = (v3 > 0.f) ? v3 : 0.01f * v3;
            }
            if (r0 < M)
                *reinterpret_cast<float2*>(out + r0 * F + col) = make_float2(v0, v1);
            if (r0 + 8 < M)
                *reinterpret_cast<float2*>(out + (r0 + 8) * F + col) = make_float2(v2, v3);
        }
    }
}

// ---------------- edge MLP (one warp per edge) ----------------
__global__ void __launch_bounds__(256) k_edge(
    const int* __restrict__ src, const int* __restrict__ dst,
    const float* __restrict__ efeat, const float* __restrict__ mw1,
    const float* __restrict__ mw2, const float* __restrict__ mb2,
    float* __restrict__ out)
{
    int w    = (blockIdx.x * blockDim.x + threadIdx.x) >> 5;
    int lane = threadIdx.x & 31;
    if (w >= NEDGES) return;
    int s = src[w], d = dst[w];
    float e = efeat[w];
    int f0 = lane * 4;

    float4 a  = *reinterpret_cast<const float4*>(g_A + s * F + f0);
    float4 b  = *reinterpret_cast<const float4*>(g_B + d * F + f0);
    float4 wr = *reinterpret_cast<const float4*>(mw1 + 256 * F + f0);

    float4 hv;
    hv.x = fmaxf(fmaf(e, wr.x, a.x + b.x), 0.f);
    hv.y = fmaxf(fmaf(e, wr.y, a.y + b.y), 0.f);
    hv.z = fmaxf(fmaf(e, wr.z, a.z + b.z), 0.f);
    hv.w = fmaxf(fmaf(e, wr.w, a.w + b.w), 0.f);

    // mw2 is [128][2]
    float4 q0 = *reinterpret_cast<const float4*>(mw2 + f0 * 2);
    float4 q1 = *reinterpret_cast<const float4*>(mw2 + f0 * 2 + 4);
    float p0 = hv.x * q0.x + hv.y * q0.z + hv.z * q1.x + hv.w * q1.z;
    float p1 = hv.x * q0.y + hv.y * q0.w + hv.z * q1.y + hv.w * q1.w;

#pragma unroll
    for (int off = 16; off; off >>= 1) {
        p0 += __shfl_xor_sync(0xffffffffu, p0, off);
        p1 += __shfl_xor_sync(0xffffffffu, p1, off);
    }
    if (lane == 0) {
        out[2 * w]     = p0 + mb2[0];
        out[2 * w + 1] = p1 + mb2[1];
    }
}

// ---------------- launch ----------------
extern "C" void kernel_launch(void* const* d_in, const int* in_sizes, int n_in,
                              void* d_out, int out_size) {
    const float* node = (const float*)d_in[0];
    const float* ef   = (const float*)d_in[1];
    const int*   src  = (const int*)d_in[2];
    const int*   dst  = (const int*)d_in[3];
    const float* ws0 = (const float*)d_in[4];
    const float* wn0 = (const float*)d_in[5];
    const float* b0  = (const float*)d_in[6];
    const float* ws1 = (const float*)d_in[7];
    const float* wn1 = (const float*)d_in[8];
    const float* b1  = (const float*)d_in[9];
    const float* ws2 = (const float*)d_in[10];
    const float* wn2 = (const float*)d_in[11];
    const float* b2  = (const float*)d_in[12];
    const float* mw1 = (const float*)d_in[13];
    const float* mb1 = (const float*)d_in[14];
    const float* mw2 = (const float*)d_in[15];
    const float* mb2 = (const float*)d_in[16];
    float* out = (float*)d_out;

    float *h0, *h1, *pA, *pB, *pm;
    cudaGetSymbolAddress((void**)&h0, g_h0);
    cudaGetSymbolAddress((void**)&h1, g_h1);
    cudaGetSymbolAddress((void**)&pA, g_A);
    cudaGetSymbolAddress((void**)&pB, g_B);
    cudaGetSymbolAddress((void**)&pm, g_mean);

    // CSR build (once, reused for all 3 layers)
    k_zero_deg<<<(NNODES + 255) / 256, 256>>>();
    k_hist<<<(NEDGES + 255) / 256, 256>>>(dst);
    k_scan1<<<NSCAN, SCAN_T>>>();
    k_scan2<<<1, 32>>>();
    k_scan3<<<(NNODES + 255) / 256, 256>>>();
    k_scatter<<<(NEDGES + 255) / 256, 256>>>(src, dst);

    const int aggBlocks  = (NNODES * 32 + 255) / 256;
    const int gemmBlocks = (NNODES + 127) / 128;
    const int edgeBlocks = (NEDGES * 32 + 255) / 256;

    // layer 0: node_feats -> h0
    k_aggmean<<<aggBlocks, 256>>>(node);
    gemm_tc<true, true><<<gemmBlocks, 256>>>(node, ws0, pm, wn0, b0, h0, NNODES);
    // layer 1: h0 -> h1
    k_aggmean<<<aggBlocks, 256>>>(h0);
    gemm_tc<true, true><<<gemmBlocks, 256>>>(h0, ws1, pm, wn1, b1, h1, NNODES);
    // layer 2: h1 -> h0
    k_aggmean<<<aggBlocks, 256>>>(h1);
    gemm_tc<true, true><<<gemmBlocks, 256>>>(h1, ws2, pm, wn2, b2, h0, NNODES);

    // node-level precompute of the factored edge MLP:
    // A = h @ mw1[0:128] + mb1 ;  B = h @ mw1[128:256]
    gemm_tc<false, false><<<gemmBlocks, 256>>>(h0, mw1, nullptr, nullptr, mb1, pA, NNODES);
    gemm_tc<false, false><<<gemmBlocks, 256>>>(h0, mw1 + 128 * F, nullptr, nullptr, nullptr, pB, NNODES);

    // edge MLP
    k_edge<<<edgeBlocks, 256>>>(src, dst, ef, mw1, mw2, mb2, out);
}

// round 7
// speedup vs baseline: 1.4343x; 1.4343x over previous
#include <cuda_runtime.h>
#include <cuda_bf16.h>

#define NNODES 100000
#define NEDGES 1600000
#define F 128
#define SCAN_T 1024
#define NSCAN ((NNODES + SCAN_T - 1) / SCAN_T)   // 98

typedef unsigned int u32;

// ---------------- scratch (static __device__, no allocs) ----------------
__device__ int   g_deg[NNODES];
__device__ float g_invdeg[NNODES];
__device__ int   g_rowptr[NNODES + 1];
__device__ int   g_cursor[NNODES];
__device__ int   g_csrsrc[NEDGES];
__device__ int   g_partials[NSCAN];
__device__ int   g_scanbuf[NNODES];
// split-bf16x2 packed node matrices (hi = low 16 bits, lo = high 16 bits)
__device__ u32   g_ns[NNODES * F];      // split node_feats
__device__ u32   g_hs0[NNODES * F];     // split h buffers
__device__ u32   g_hs1[NNODES * F];
__device__ u32   g_means[NNODES * F];   // split mean_neigh
__device__ u32   g_wt[8 * F * F];       // split+transposed weights [n][k]
__device__ float g_A[NNODES * F];       // fp32 edge precomputes
__device__ float g_B[NNODES * F];

// ---------------- helpers ----------------
__device__ __forceinline__ u32 prmt(u32 a, u32 b, u32 s) {
    u32 d;
    asm("prmt.b32 %0,%1,%2,%3;" : "=r"(d) : "r"(a), "r"(b), "r"(s));
    return d;
}
// pack fp32 as (hi_bf16 | lo_bf16<<16), value = hi + lo
__device__ __forceinline__ u32 packsplit(float v) {
    __nv_bfloat16 h = __float2bfloat16_rn(v);
    float r = v - __bfloat162float(h);
    __nv_bfloat16 l = __float2bfloat16_rn(r);
    __nv_bfloat162 p(h, l);
    return *reinterpret_cast<u32*>(&p);
}
__device__ __forceinline__ float unpacksplit(u32 u) {
    __nv_bfloat162 b = *reinterpret_cast<__nv_bfloat162*>(&u);
    float2 f = __bfloat1622float2(b);
    return f.x + f.y;
}

// ---------------- one-time split kernels ----------------
__global__ void k_split(const float* __restrict__ in, u32* __restrict__ out, int n) {
    int i = blockIdx.x * blockDim.x + threadIdx.x;
    if (i < n) out[i] = packsplit(in[i]);
}
// W is [K=128][N=128] row-major; out is [n][k] (transposed), split-packed
__global__ void k_splitwt(const float* __restrict__ in, u32* __restrict__ out) {
    int idx = blockIdx.x * blockDim.x + threadIdx.x;   // = n*128 + k
    if (idx < F * F) {
        int n = idx >> 7, k = idx & 127;
        out[idx] = packsplit(in[k * F + n]);
    }
}

// ---------------- CSR build ----------------
__global__ void k_zero_deg() {
    int i = blockIdx.x * blockDim.x + threadIdx.x;
    if (i < NNODES) g_deg[i] = 0;
}

__global__ void k_hist(const int* __restrict__ dst) {
    int e = blockIdx.x * blockDim.x + threadIdx.x;
    if (e < NEDGES) atomicAdd(&g_deg[dst[e]], 1);
}

__global__ void k_scan1() {
    __shared__ int sd[SCAN_T];
    int t = threadIdx.x;
    int i = blockIdx.x * SCAN_T + t;
    int v = (i < NNODES) ? g_deg[i] : 0;
    sd[t] = v;
    __syncthreads();
    for (int off = 1; off < SCAN_T; off <<= 1) {
        int add = (t >= off) ? sd[t - off] : 0;
        __syncthreads();
        sd[t] += add;
        __syncthreads();
    }
    if (i < NNODES) g_scanbuf[i] = sd[t];
    if (t == SCAN_T - 1) g_partials[blockIdx.x] = sd[t];
}

__global__ void k_scan2() {
    if (threadIdx.x == 0) {
        int run = 0;
        for (int b = 0; b < NSCAN; b++) {
            int p = g_partials[b];
            g_partials[b] = run;
            run += p;
        }
    }
}

__global__ void k_scan3() {
    int i = blockIdx.x * blockDim.x + threadIdx.x;
    if (i < NNODES) {
        int incl = g_scanbuf[i] + g_partials[i >> 10];
        int d = g_deg[i];
        int excl = incl - d;
        g_rowptr[i] = excl;
        g_cursor[i] = excl;
        g_invdeg[i] = 1.0f / fmaxf((float)d, 1.0f);
        if (i == 0) g_rowptr[NNODES] = NEDGES;
    }
}

__global__ void k_scatter(const int* __restrict__ src, const int* __restrict__ dst) {
    int e = blockIdx.x * blockDim.x + threadIdx.x;
    if (e < NEDGES) {
        int pos = atomicAdd(&g_cursor[dst[e]], 1);
        g_csrsrc[pos] = src[e];
    }
}

// ---------------- mean aggregation over split arrays ----------------
__global__ void __launch_bounds__(256) k_aggmean(const u32* __restrict__ hs) {
    int w    = (blockIdx.x * blockDim.x + threadIdx.x) >> 5;
    int lane = threadIdx.x & 31;
    if (w >= NNODES) return;
    int beg = g_rowptr[w], end = g_rowptr[w + 1];
    int f0 = lane * 4;
    float4 acc = make_float4(0.f, 0.f, 0.f, 0.f);
    for (int i = beg; i < end; i += 32) {
        int n = min(32, end - i);
        int sidx = (lane < n) ? g_csrsrc[i + lane] : 0;
        int j = 0;
        for (; j + 4 <= n; j += 4) {
            int s0 = __shfl_sync(0xffffffffu, sidx, j + 0);
            int s1 = __shfl_sync(0xffffffffu, sidx, j + 1);
            int s2 = __shfl_sync(0xffffffffu, sidx, j + 2);
            int s3 = __shfl_sync(0xffffffffu, sidx, j + 3);
            uint4 v0 = *reinterpret_cast<const uint4*>(hs + s0 * F + f0);
            uint4 v1 = *reinterpret_cast<const uint4*>(hs + s1 * F + f0);
            uint4 v2 = *reinterpret_cast<const uint4*>(hs + s2 * F + f0);
            uint4 v3 = *reinterpret_cast<const uint4*>(hs + s3 * F + f0);
            acc.x += unpacksplit(v0.x) + unpacksplit(v1.x) + unpacksplit(v2.x) + unpacksplit(v3.x);
            acc.y += unpacksplit(v0.y) + unpacksplit(v1.y) + unpacksplit(v2.y) + unpacksplit(v3.y);
            acc.z += unpacksplit(v0.z) + unpacksplit(v1.z) + unpacksplit(v2.z) + unpacksplit(v3.z);
            acc.w += unpacksplit(v0.w) + unpacksplit(v1.w) + unpacksplit(v2.w) + unpacksplit(v3.w);
        }
        for (; j < n; j++) {
            int s = __shfl_sync(0xffffffffu, sidx, j);
            uint4 v = *reinterpret_cast<const uint4*>(hs + s * F + f0);
            acc.x += unpacksplit(v.x); acc.y += unpacksplit(v.y);
            acc.z += unpacksplit(v.z); acc.w += unpacksplit(v.w);
        }
    }
    float sc = g_invdeg[w];
    uint4 o;
    o.x = packsplit(acc.x * sc); o.y = packsplit(acc.y * sc);
    o.z = packsplit(acc.z * sc); o.w = packsplit(acc.w * sc);
    *reinterpret_cast<uint4*>(g_means + w * F + f0) = o;
}

// ---------------- tensor-core GEMM on pre-split data ----------------
// out = X1@W1 (+ X2@W2) (+bias) (+leaky), fp32 math via 3-pass bf16 split MMA.
// X arrays: [row][k] split-packed u32. W arrays: [n][k] split-packed u32.
// BM=128 BN=128 BK=32-chunks, 256 threads (2x4 warps, warp tile 64x32).

__device__ __forceinline__ void mma_bf16(float* c, const u32* a, const u32* b) {
    asm volatile(
        "mma.sync.aligned.m16n8k16.row.col.f32.bf16.bf16.f32 "
        "{%0,%1,%2,%3}, {%4,%5,%6,%7}, {%8,%9}, {%0,%1,%2,%3};"
        : "+f"(c[0]), "+f"(c[1]), "+f"(c[2]), "+f"(c[3])
        : "r"(a[0]), "r"(a[1]), "r"(a[2]), "r"(a[3]), "r"(b[0]), "r"(b[1]));
}

#define SPAD 40   // bf16 row stride: 80B -> conflict-free frag LDS

template <bool HAS2, bool LEAKY, bool SPLITOUT>
__global__ void __launch_bounds__(256) gemm_tcs(
    const u32* __restrict__ X1, const u32* __restrict__ W1,
    const u32* __restrict__ X2, const u32* __restrict__ W2,
    const float* __restrict__ bias, void* __restrict__ outv, int M)
{
    __shared__ alignas(16) __nv_bfloat16 sAh[128][SPAD];
    __shared__ alignas(16) __nv_bfloat16 sAl[128][SPAD];
    __shared__ alignas(16) __nv_bfloat16 sWh[128][SPAD];
    __shared__ alignas(16) __nv_bfloat16 sWl[128][SPAD];

    const int tid  = threadIdx.x;
    const int lane = tid & 31;
    const int g    = lane >> 2;
    const int tg   = lane & 3;
    const int wm   = (tid >> 5) >> 2;   // 0..1
    const int wn   = (tid >> 5) & 3;    // 0..3
    const int rowBase = blockIdx.x * 128;

    float acc[4][4][4];
#pragma unroll
    for (int mt = 0; mt < 4; mt++)
#pragma unroll
        for (int nt = 0; nt < 4; nt++)
#pragma unroll
            for (int q = 0; q < 4; q++) acc[mt][nt][q] = 0.f;

    const int NCHUNK = HAS2 ? 8 : 4;
    uint4 ra[4], rw[4];

    // prefetch chunk 0
    {
        const u32* Xp = X1; const u32* Wp = W1;
#pragma unroll
        for (int i = 0; i < 4; i++) {
            int idx4 = tid + i * 256;
            int row = idx4 >> 3, c4 = (idx4 & 7) << 2;
            int grow = rowBase + row;
            ra[i] = (grow < M) ? *reinterpret_cast<const uint4*>(Xp + grow * F + c4)
                               : make_uint4(0u, 0u, 0u, 0u);
            rw[i] = *reinterpret_cast<const uint4*>(Wp + row * F + c4);
        }
    }

    for (int c = 0; c < NCHUNK; c++) {
        __syncthreads();   // prior compute done reading smem
        // store current regs to smem (de-interleave hi/lo via PRMT)
#pragma unroll
        for (int i = 0; i < 4; i++) {
            int idx4 = tid + i * 256;
            int row = idx4 >> 3, c4 = (idx4 & 7) << 2;
            u32 hi01 = prmt(ra[i].x, ra[i].y, 0x5410u);
            u32 lo01 = prmt(ra[i].x, ra[i].y, 0x7632u);
            u32 hi23 = prmt(ra[i].z, ra[i].w, 0x5410u);
            u32 lo23 = prmt(ra[i].z, ra[i].w, 0x7632u);
            *reinterpret_cast<uint2*>(&sAh[row][c4]) = make_uint2(hi01, hi23);
            *reinterpret_cast<uint2*>(&sAl[row][c4]) = make_uint2(lo01, lo23);
            hi01 = prmt(rw[i].x, rw[i].y, 0x5410u);
            lo01 = prmt(rw[i].x, rw[i].y, 0x7632u);
            hi23 = prmt(rw[i].z, rw[i].w, 0x5410u);
            lo23 = prmt(rw[i].z, rw[i].w, 0x7632u);
            *reinterpret_cast<uint2*>(&sWh[row][c4]) = make_uint2(hi01, hi23);
            *reinterpret_cast<uint2*>(&sWl[row][c4]) = make_uint2(lo01, lo23);
        }
        __syncthreads();

        // prefetch next chunk into regs (overlaps with MMA below)
        if (c + 1 < NCHUNK) {
            int cn = c + 1;
            const u32* Xp = (cn < 4) ? X1 : X2;
            const u32* Wp = (cn < 4) ? W1 : W2;
            const int k0 = (cn & 3) * 32;
#pragma unroll
            for (int i = 0; i < 4; i++) {
                int idx4 = tid + i * 256;
                int row = idx4 >> 3, c4 = (idx4 & 7) << 2;
                int grow = rowBase + row;
                ra[i] = (grow < M) ? *reinterpret_cast<const uint4*>(Xp + grow * F + k0 + c4)
                                   : make_uint4(0u, 0u, 0u, 0u);
                rw[i] = *reinterpret_cast<const uint4*>(Wp + row * F + k0 + c4);
            }
        }

        // compute: 2 k16-steps, 3 split passes each
#pragma unroll
        for (int kk = 0; kk < 2; kk++) {
            const int kb = kk * 16 + tg * 2;
            u32 bh[4][2], bl[4][2];
#pragma unroll
            for (int nt = 0; nt < 4; nt++) {
                const int n0 = wn * 32 + nt * 8 + g;
                bh[nt][0] = *reinterpret_cast<const u32*>(&sWh[n0][kb]);
                bh[nt][1] = *reinterpret_cast<const u32*>(&sWh[n0][kb + 8]);
                bl[nt][0] = *reinterpret_cast<const u32*>(&sWl[n0][kb]);
                bl[nt][1] = *reinterpret_cast<const u32*>(&sWl[n0][kb + 8]);
            }
#pragma unroll
            for (int mt = 0; mt < 4; mt++) {
                const int r0 = wm * 64 + mt * 16 + g;
                u32 ah[4], al[4];
                ah[0] = *reinterpret_cast<const u32*>(&sAh[r0][kb]);
                ah[1] = *reinterpret_cast<const u32*>(&sAh[r0 + 8][kb]);
                ah[2] = *reinterpret_cast<const u32*>(&sAh[r0][kb + 8]);
                ah[3] = *reinterpret_cast<const u32*>(&sAh[r0 + 8][kb + 8]);
#pragma unroll
                for (int nt = 0; nt < 4; nt++) mma_bf16(acc[mt][nt], ah, bh[nt]);
#pragma unroll
                for (int nt = 0; nt < 4; nt++) mma_bf16(acc[mt][nt], ah, bl[nt]);
                al[0] = *reinterpret_cast<const u32*>(&sAl[r0][kb]);
                al[1] = *reinterpret_cast<const u32*>(&sAl[r0 + 8][kb]);
                al[2] = *reinterpret_cast<const u32*>(&sAl[r0][kb + 8]);
                al[3] = *reinterpret_cast<const u32*>(&sAl[r0 + 8][kb + 8]);
#pragma unroll
                for (int nt = 0; nt < 4; nt++) mma_bf16(acc[mt][nt], al, bh[nt]);
            }
        }
    }

    // ---- epilogue ----
#pragma unroll
    for (int nt = 0; nt < 4; nt++) {
        const int col = wn * 32 + nt * 8 + tg * 2;
        const float b0v = bias ? bias[col]     : 0.f;
        const float b1v = bias ? bias[col + 1] : 0.f;
#pragma unroll
        for (int mt = 0; mt < 4; mt++) {
            const int r0 = rowBase + wm * 64 + mt * 16 + g;
            float v0 = acc[mt][nt][0] + b0v;
            float v1 = acc[mt][nt][1] + b1v;
            float v2 = acc[mt][nt][2] + b0v;
            float v3 = acc[mt][nt][3] + b1v;
            if (LEAKY) {
                v0 = (v0 > 0.f) ? v0 : 0.01f * v0;
                v1 = (v1 > 0.f) ? v1 : 0.01f * v1;
                v2 = (v2 > 0.f) ? v2 : 0.01f * v2;
                v3 = (v3 > 0.f) ? v3 : 0.01f * v3;
            }
            if (SPLITOUT) {
                u32* out = reinterpret_cast<u32*>(outv);
                if (r0 < M)
                    *reinterpret_cast<uint2*>(out + r0 * F + col) =
                        make_uint2(packsplit(v0), packsplit(v1));
                if (r0 + 8 < M)
                    *reinterpret_cast<uint2*>(out + (r0 + 8) * F + col) =
                        make_uint2(packsplit(v2), packsplit(v3));
            } else {
                float* out = reinterpret_cast<float*>(outv);
                if (r0 < M)
                    *reinterpret_cast<float2*>(out + r0 * F + col) = make_float2(v0, v1);
                if (r0 + 8 < M)
                    *reinterpret_cast<float2*>(out + (r0 + 8) * F + col) = make_float2(v2, v3);
            }
        }
    }
}

// ---------------- edge MLP (one warp per edge) ----------------
__global__ void __launch_bounds__(256) k_edge(
    const int* __restrict__ src, const int* __restrict__ dst,
    const float* __restrict__ efeat, const float* __restrict__ mw1,
    const float* __restrict__ mw2, const float* __restrict__ mb2,
    float* __restrict__ out)
{
    int w    = (blockIdx.x * blockDim.x + threadIdx.x) >> 5;
    int lane = threadIdx.x & 31;
    if (w >= NEDGES) return;
    int s = src[w], d = dst[w];
    float e = efeat[w];
    int f0 = lane * 4;

    float4 a  = *reinterpret_cast<const float4*>(g_A + s * F + f0);
    float4 b  = *reinterpret_cast<const float4*>(g_B + d * F + f0);
    float4 wr = *reinterpret_cast<const float4*>(mw1 + 256 * F + f0);

    float4 hv;
    hv.x = fmaxf(fmaf(e, wr.x, a.x + b.x), 0.f);
    hv.y = fmaxf(fmaf(e, wr.y, a.y + b.y), 0.f);
    hv.z = fmaxf(fmaf(e, wr.z, a.z + b.z), 0.f);
    hv.w = fmaxf(fmaf(e, wr.w, a.w + b.w), 0.f);

    // mw2 is [128][2]
    float4 q0 = *reinterpret_cast<const float4*>(mw2 + f0 * 2);
    float4 q1 = *reinterpret_cast<const float4*>(mw2 + f0 * 2 + 4);
    float p0 = hv.x * q0.x + hv.y * q0.z + hv.z * q1.x + hv.w * q1.z;
    float p1 = hv.x * q0.y + hv.y * q0.w + hv.z * q1.y + hv.w * q1.w;

#pragma unroll
    for (int off = 16; off; off >>= 1) {
        p0 += __shfl_xor_sync(0xffffffffu, p0, off);
        p1 += __shfl_xor_sync(0xffffffffu, p1, off);
    }
    if (lane == 0) {
        out[2 * w]     = p0 + mb2[0];
        out[2 * w + 1] = p1 + mb2[1];
    }
}

// ---------------- launch ----------------
extern "C" void kernel_launch(void* const* d_in, const int* in_sizes, int n_in,
                              void* d_out, int out_size) {
    const float* node = (const float*)d_in[0];
    const float* ef   = (const float*)d_in[1];
    const int*   src  = (const int*)d_in[2];
    const int*   dst  = (const int*)d_in[3];
    const float* ws0 = (const float*)d_in[4];
    const float* wn0 = (const float*)d_in[5];
    const float* b0  = (const float*)d_in[6];
    const float* ws1 = (const float*)d_in[7];
    const float* wn1 = (const float*)d_in[8];
    const float* b1  = (const float*)d_in[9];
    const float* ws2 = (const float*)d_in[10];
    const float* wn2 = (const float*)d_in[11];
    const float* b2  = (const float*)d_in[12];
    const float* mw1 = (const float*)d_in[13];
    const float* mb1 = (const float*)d_in[14];
    const float* mw2 = (const float*)d_in[15];
    const float* mb2 = (const float*)d_in[16];
    float* out = (float*)d_out;

    u32 *ns, *hs0, *hs1, *means, *wt;
    float *pA, *pB;
    cudaGetSymbolAddress((void**)&ns,    g_ns);
    cudaGetSymbolAddress((void**)&hs0,   g_hs0);
    cudaGetSymbolAddress((void**)&hs1,   g_hs1);
    cudaGetSymbolAddress((void**)&means, g_means);
    cudaGetSymbolAddress((void**)&wt,    g_wt);
    cudaGetSymbolAddress((void**)&pA,    g_A);
    cudaGetSymbolAddress((void**)&pB,    g_B);

    u32* wt_ws0 = wt + 0 * F * F;
    u32* wt_wn0 = wt + 1 * F * F;
    u32* wt_ws1 = wt + 2 * F * F;
    u32* wt_wn1 = wt + 3 * F * F;
    u32* wt_ws2 = wt + 4 * F * F;
    u32* wt_wn2 = wt + 5 * F * F;
    u32* wt_m1a = wt + 6 * F * F;
    u32* wt_m1b = wt + 7 * F * F;

    // one-time splits
    k_split<<<(NNODES * F + 255) / 256, 256>>>(node, ns, NNODES * F);
    k_splitwt<<<64, 256>>>(ws0, wt_ws0);
    k_splitwt<<<64, 256>>>(wn0, wt_wn0);
    k_splitwt<<<64, 256>>>(ws1, wt_ws1);
    k_splitwt<<<64, 256>>>(wn1, wt_wn1);
    k_splitwt<<<64, 256>>>(ws2, wt_ws2);
    k_splitwt<<<64, 256>>>(wn2, wt_wn2);
    k_splitwt<<<64, 256>>>(mw1, wt_m1a);            // rows 0..127
    k_splitwt<<<64, 256>>>(mw1 + 128 * F, wt_m1b);  // rows 128..255

    // CSR build (once, reused for all 3 layers)
    k_zero_deg<<<(NNODES + 255) / 256, 256>>>();
    k_hist<<<(NEDGES + 255) / 256, 256>>>(dst);
    k_scan1<<<NSCAN, SCAN_T>>>();
    k_scan2<<<1, 32>>>();
    k_scan3<<<(NNODES + 255) / 256, 256>>>();
    k_scatter<<<(NEDGES + 255) / 256, 256>>>(src, dst);

    const int aggBlocks  = (NNODES * 32 + 255) / 256;
    const int gemmBlocks = (NNODES + 127) / 128;
    const int edgeBlocks = (NEDGES * 32 + 255) / 256;

    // layer 0
    k_aggmean<<<aggBlocks, 256>>>(ns);
    gemm_tcs<true, true, true><<<gemmBlocks, 256>>>(ns, wt_ws0, means, wt_wn0, b0, hs0, NNODES);
    // layer 1
    k_aggmean<<<aggBlocks, 256>>>(hs0);
    gemm_tcs<true, true, true><<<gemmBlocks, 256>>>(hs0, wt_ws1, means, wt_wn1, b1, hs1, NNODES);
    // layer 2
    k_aggmean<<<aggBlocks, 256>>>(hs1);
    gemm_tcs<true, true, true><<<gemmBlocks, 256>>>(hs1, wt_ws2, means, wt_wn2, b2, hs0, NNODES);

    // factored edge MLP node precomputes: A = h@mw1[0:128]+mb1, B = h@mw1[128:256]
    gemm_tcs<false, false, false><<<gemmBlocks, 256>>>(hs0, wt_m1a, nullptr, nullptr, mb1, pA, NNODES);
    gemm_tcs<false, false, false><<<gemmBlocks, 256>>>(hs0, wt_m1b, nullptr, nullptr, nullptr, pB, NNODES);

    // edge MLP
    k_edge<<<edgeBlocks, 256>>>(src, dst, ef, mw1, mw2, mb2, out);
}

// round 9
// speedup vs baseline: 1.7972x; 1.2531x over previous
#include <cuda_runtime.h>
#include <cuda_bf16.h>

#define NNODES 100000
#define NEDGES 1600000
#define F 128
#define SCAN_T 1024
#define NSCAN ((NNODES + SCAN_T - 1) / SCAN_T)   // 98

typedef unsigned int u32;

// ---------------- scratch (static __device__, no allocs) ----------------
__device__ int   g_deg[NNODES];
__device__ float g_invdeg[NNODES];
__device__ int   g_rowptr[NNODES + 1];
__device__ int   g_cursor[NNODES];
__device__ int   g_csrsrc[NEDGES];
__device__ int   g_csredge[NEDGES];
__device__ int   g_partials[NSCAN];
__device__ int   g_scanbuf[NNODES];
// split-bf16x2 packed node matrices (hi = low 16 bits, lo = high 16 bits)
__device__ u32   g_ns[NNODES * F];      // split node_feats
__device__ u32   g_hs0[NNODES * F];     // split h buffers
__device__ u32   g_hs1[NNODES * F];
__device__ u32   g_means[NNODES * F];   // split mean_neigh
__device__ u32   g_wt[8 * F * F];       // split+transposed weights [n][k]
__device__ float g_A[NNODES * F];       // fp32 edge precomputes
__device__ float g_B[NNODES * F];

// ---------------- helpers ----------------
__device__ __forceinline__ u32 prmt(u32 a, u32 b, u32 s) {
    u32 d;
    asm("prmt.b32 %0,%1,%2,%3;" : "=r"(d) : "r"(a), "r"(b), "r"(s));
    return d;
}
// pack fp32 as (hi_bf16 | lo_bf16<<16), value = hi + lo
__device__ __forceinline__ u32 packsplit(float v) {
    __nv_bfloat16 h = __float2bfloat16_rn(v);
    float r = v - __bfloat162float(h);
    __nv_bfloat16 l = __float2bfloat16_rn(r);
    __nv_bfloat162 p(h, l);
    return *reinterpret_cast<u32*>(&p);
}
__device__ __forceinline__ float unpacksplit(u32 u) {
    __nv_bfloat162 b = *reinterpret_cast<__nv_bfloat162*>(&u);
    float2 f = __bfloat1622float2(b);
    return f.x + f.y;
}

// ---------------- one-time split kernels ----------------
__global__ void k_split(const float* __restrict__ in, u32* __restrict__ out, int n) {
    int i = blockIdx.x * blockDim.x + threadIdx.x;
    if (i < n) out[i] = packsplit(in[i]);
}
// All 8 weight matrices in one launch. Each W is [K=128][N=128] row-major;
// out slot m is [n][k] (transposed), split-packed.
struct WPtrs { const float* p[8]; };
__global__ void k_splitwt8(WPtrs wp, u32* __restrict__ out) {
    int idx = blockIdx.x * blockDim.x + threadIdx.x;   // < 8*128*128
    int m = idx >> 14;
    int r = idx & 16383;
    int n = r >> 7, k = r & 127;
    out[idx] = packsplit(wp.p[m][k * F + n]);
}

// ---------------- CSR build ----------------
__global__ void k_zero_deg() {
    int i = blockIdx.x * blockDim.x + threadIdx.x;
    if (i < NNODES) g_deg[i] = 0;
}

__global__ void k_hist(const int* __restrict__ dst) {
    int e = blockIdx.x * blockDim.x + threadIdx.x;
    if (e < NEDGES) atomicAdd(&g_deg[dst[e]], 1);
}

__global__ void k_scan1() {
    __shared__ int sd[SCAN_T];
    int t = threadIdx.x;
    int i = blockIdx.x * SCAN_T + t;
    int v = (i < NNODES) ? g_deg[i] : 0;
    sd[t] = v;
    __syncthreads();
    for (int off = 1; off < SCAN_T; off <<= 1) {
        int add = (t >= off) ? sd[t - off] : 0;
        __syncthreads();
        sd[t] += add;
        __syncthreads();
    }
    if (i < NNODES) g_scanbuf[i] = sd[t];
    if (t == SCAN_T - 1) g_partials[blockIdx.x] = sd[t];
}

__global__ void k_scan2() {
    if (threadIdx.x == 0) {
        int run = 0;
        for (int b = 0; b < NSCAN; b++) {
            int p = g_partials[b];
            g_partials[b] = run;
            run += p;
        }
    }
}

__global__ void k_scan3() {
    int i = blockIdx.x * blockDim.x + threadIdx.x;
    if (i < NNODES) {
        int incl = g_scanbuf[i] + g_partials[i >> 10];
        int d = g_deg[i];
        int excl = incl - d;
        g_rowptr[i] = excl;
        g_cursor[i] = excl;
        g_invdeg[i] = 1.0f / fmaxf((float)d, 1.0f);
        if (i == 0) g_rowptr[NNODES] = NEDGES;
    }
}

__global__ void k_scatter(const int* __restrict__ src, const int* __restrict__ dst) {
    int e = blockIdx.x * blockDim.x + threadIdx.x;
    if (e < NEDGES) {
        int pos = atomicAdd(&g_cursor[dst[e]], 1);
        g_csrsrc[pos] = src[e];
        g_csredge[pos] = e;
    }
}

// ---------------- mean aggregation over split arrays ----------------
__global__ void __launch_bounds__(256) k_aggmean(const u32* __restrict__ hs) {
    int w    = (blockIdx.x * blockDim.x + threadIdx.x) >> 5;
    int lane = threadIdx.x & 31;
    if (w >= NNODES) return;
    int beg = g_rowptr[w], end = g_rowptr[w + 1];
    int f0 = lane * 4;
    float4 acc = make_float4(0.f, 0.f, 0.f, 0.f);
    for (int i = beg; i < end; i += 32) {
        int n = min(32, end - i);
        int sidx = (lane < n) ? g_csrsrc[i + lane] : 0;
        int j = 0;
        for (; j + 4 <= n; j += 4) {
            int s0 = __shfl_sync(0xffffffffu, sidx, j + 0);
            int s1 = __shfl_sync(0xffffffffu, sidx, j + 1);
            int s2 = __shfl_sync(0xffffffffu, sidx, j + 2);
            int s3 = __shfl_sync(0xffffffffu, sidx, j + 3);
            uint4 v0 = *reinterpret_cast<const uint4*>(hs + s0 * F + f0);
            uint4 v1 = *reinterpret_cast<const uint4*>(hs + s1 * F + f0);
            uint4 v2 = *reinterpret_cast<const uint4*>(hs + s2 * F + f0);
            uint4 v3 = *reinterpret_cast<const uint4*>(hs + s3 * F + f0);
            acc.x += unpacksplit(v0.x) + unpacksplit(v1.x) + unpacksplit(v2.x) + unpacksplit(v3.x);
            acc.y += unpacksplit(v0.y) + unpacksplit(v1.y) + unpacksplit(v2.y) + unpacksplit(v3.y);
            acc.z += unpacksplit(v0.z) + unpacksplit(v1.z) + unpacksplit(v2.z) + unpacksplit(v3.z);
            acc.w += unpacksplit(v0.w) + unpacksplit(v1.w) + unpacksplit(v2.w) + unpacksplit(v3.w);
        }
        for (; j < n; j++) {
            int s = __shfl_sync(0xffffffffu, sidx, j);
            uint4 v = *reinterpret_cast<const uint4*>(hs + s * F + f0);
            acc.x += unpacksplit(v.x); acc.y += unpacksplit(v.y);
            acc.z += unpacksplit(v.z); acc.w += unpacksplit(v.w);
        }
    }
    float sc = g_invdeg[w];
    uint4 o;
    o.x = packsplit(acc.x * sc); o.y = packsplit(acc.y * sc);
    o.z = packsplit(acc.z * sc); o.w = packsplit(acc.w * sc);
    *reinterpret_cast<uint4*>(g_means + w * F + f0) = o;
}

// ---------------- tensor-core GEMM on pre-split data ----------------
// out = X1@W1 (+ X2@W2) (+bias) (+leaky), fp32 math via 3-pass bf16 split MMA.
// X arrays: [row][k] split-packed u32. W arrays: [n][k] split-packed u32.
// BM=128 BN=128 BK=32-chunks, 256 threads (2x4 warps, warp tile 64x32).
// DUAL: gridDim.y=2 computes a second product X1@W1b -> outvb (no bias).

__device__ __forceinline__ void mma_bf16(float* c, const u32* a, const u32* b) {
    asm volatile(
        "mma.sync.aligned.m16n8k16.row.col.f32.bf16.bf16.f32 "
        "{%0,%1,%2,%3}, {%4,%5,%6,%7}, {%8,%9}, {%0,%1,%2,%3};"
        : "+f"(c[0]), "+f"(c[1]), "+f"(c[2]), "+f"(c[3])
        : "r"(a[0]), "r"(a[1]), "r"(a[2]), "r"(a[3]), "r"(b[0]), "r"(b[1]));
}

#define SPAD 40   // bf16 row stride: 80B -> conflict-free frag LDS

template <bool HAS2, bool LEAKY, bool SPLITOUT, bool DUAL>
__global__ void __launch_bounds__(256) gemm_tcs(
    const u32* __restrict__ X1, const u32* __restrict__ W1,
    const u32* __restrict__ X2, const u32* __restrict__ W2,
    const float* __restrict__ bias, void* __restrict__ outv,
    const u32* __restrict__ W1b, void* __restrict__ outvb, int M)
{
    if (DUAL && blockIdx.y == 1) {
        W1 = W1b;
        outv = outvb;
        bias = nullptr;
    }

    __shared__ alignas(16) __nv_bfloat16 sAh[128][SPAD];
    __shared__ alignas(16) __nv_bfloat16 sAl[128][SPAD];
    __shared__ alignas(16) __nv_bfloat16 sWh[128][SPAD];
    __shared__ alignas(16) __nv_bfloat16 sWl[128][SPAD];

    const int tid  = threadIdx.x;
    const int lane = tid & 31;
    const int g    = lane >> 2;
    const int tg   = lane & 3;
    const int wm   = (tid >> 5) >> 2;   // 0..1
    const int wn   = (tid >> 5) & 3;    // 0..3
    const int rowBase = blockIdx.x * 128;

    float acc[4][4][4];
#pragma unroll
    for (int mt = 0; mt < 4; mt++)
#pragma unroll
        for (int nt = 0; nt < 4; nt++)
#pragma unroll
            for (int q = 0; q < 4; q++) acc[mt][nt][q] = 0.f;

    const int NCHUNK = HAS2 ? 8 : 4;
    uint4 ra[4], rw[4];

    // prefetch chunk 0
    {
        const u32* Xp = X1; const u32* Wp = W1;
#pragma unroll
        for (int i = 0; i < 4; i++) {
            int idx4 = tid + i * 256;
            int row = idx4 >> 3, c4 = (idx4 & 7) << 2;
            int grow = rowBase + row;
            ra[i] = (grow < M) ? *reinterpret_cast<const uint4*>(Xp + grow * F + c4)
                               : make_uint4(0u, 0u, 0u, 0u);
            rw[i] = *reinterpret_cast<const uint4*>(Wp + row * F + c4);
        }
    }

    for (int c = 0; c < NCHUNK; c++) {
        __syncthreads();   // prior compute done reading smem
        // store current regs to smem (de-interleave hi/lo via PRMT)
#pragma unroll
        for (int i = 0; i < 4; i++) {
            int idx4 = tid + i * 256;
            int row = idx4 >> 3, c4 = (idx4 & 7) << 2;
            u32 hi01 = prmt(ra[i].x, ra[i].y, 0x5410u);
            u32 lo01 = prmt(ra[i].x, ra[i].y, 0x7632u);
            u32 hi23 = prmt(ra[i].z, ra[i].w, 0x5410u);
            u32 lo23 = prmt(ra[i].z, ra[i].w, 0x7632u);
            *reinterpret_cast<uint2*>(&sAh[row][c4]) = make_uint2(hi01, hi23);
            *reinterpret_cast<uint2*>(&sAl[row][c4]) = make_uint2(lo01, lo23);
            hi01 = prmt(rw[i].x, rw[i].y, 0x5410u);
            lo01 = prmt(rw[i].x, rw[i].y, 0x7632u);
            hi23 = prmt(rw[i].z, rw[i].w, 0x5410u);
            lo23 = prmt(rw[i].z, rw[i].w, 0x7632u);
            *reinterpret_cast<uint2*>(&sWh[row][c4]) = make_uint2(hi01, hi23);
            *reinterpret_cast<uint2*>(&sWl[row][c4]) = make_uint2(lo01, lo23);
        }
        __syncthreads();

        // prefetch next chunk into regs (overlaps with MMA below)
        if (c + 1 < NCHUNK) {
            int cn = c + 1;
            const u32* Xp = (cn < 4) ? X1 : X2;
            const u32* Wp = (cn < 4) ? W1 : W2;
            const int k0 = (cn & 3) * 32;
#pragma unroll
            for (int i = 0; i < 4; i++) {
                int idx4 = tid + i * 256;
                int row = idx4 >> 3, c4 = (idx4 & 7) << 2;
                int grow = rowBase + row;
                ra[i] = (grow < M) ? *reinterpret_cast<const uint4*>(Xp + grow * F + k0 + c4)
                                   : make_uint4(0u, 0u, 0u, 0u);
                rw[i] = *reinterpret_cast<const uint4*>(Wp + row * F + k0 + c4);
            }
        }

        // compute: 2 k16-steps, 3 split passes each
#pragma unroll
        for (int kk = 0; kk < 2; kk++) {
            const int kb = kk * 16 + tg * 2;
            u32 bh[4][2], bl[4][2];
#pragma unroll
            for (int nt = 0; nt < 4; nt++) {
                const int n0 = wn * 32 + nt * 8 + g;
                bh[nt][0] = *reinterpret_cast<const u32*>(&sWh[n0][kb]);
                bh[nt][1] = *reinterpret_cast<const u32*>(&sWh[n0][kb + 8]);
                bl[nt][0] = *reinterpret_cast<const u32*>(&sWl[n0][kb]);
                bl[nt][1] = *reinterpret_cast<const u32*>(&sWl[n0][kb + 8]);
            }
#pragma unroll
            for (int mt = 0; mt < 4; mt++) {
                const int r0 = wm * 64 + mt * 16 + g;
                u32 ah[4], al[4];
                ah[0] = *reinterpret_cast<const u32*>(&sAh[r0][kb]);
                ah[1] = *reinterpret_cast<const u32*>(&sAh[r0 + 8][kb]);
                ah[2] = *reinterpret_cast<const u32*>(&sAh[r0][kb + 8]);
                ah[3] = *reinterpret_cast<const u32*>(&sAh[r0 + 8][kb + 8]);
#pragma unroll
                for (int nt = 0; nt < 4; nt++) mma_bf16(acc[mt][nt], ah, bh[nt]);
#pragma unroll
                for (int nt = 0; nt < 4; nt++) mma_bf16(acc[mt][nt], ah, bl[nt]);
                al[0] = *reinterpret_cast<const u32*>(&sAl[r0][kb]);
                al[1] = *reinterpret_cast<const u32*>(&sAl[r0 + 8][kb]);
                al[2] = *reinterpret_cast<const u32*>(&sAl[r0][kb + 8]);
                al[3] = *reinterpret_cast<const u32*>(&sAl[r0 + 8][kb + 8]);
#pragma unroll
                for (int nt = 0; nt < 4; nt++) mma_bf16(acc[mt][nt], al, bh[nt]);
            }
        }
    }

    // ---- epilogue ----
#pragma unroll
    for (int nt = 0; nt < 4; nt++) {
        const int col = wn * 32 + nt * 8 + tg * 2;
        const float b0v = bias ? bias[col]     : 0.f;
        const float b1v = bias ? bias[col + 1] : 0.f;
#pragma unroll
        for (int mt = 0; mt < 4; mt++) {
            const int r0 = rowBase + wm * 64 + mt * 16 + g;
            float v0 = acc[mt][nt][0] + b0v;
            float v1 = acc[mt][nt][1] + b1v;
            float v2 = acc[mt][nt][2] + b0v;
            float v3 = acc[mt][nt][3] + b1v;
            if (LEAKY) {
                v0 = (v0 > 0.f) ? v0 : 0.01f * v0;
                v1 = (v1 > 0.f) ? v1 : 0.01f * v1;
                v2 = (v2 > 0.f) ? v2 : 0.01f * v2;
                v3 = (v3 > 0.f) ? v3 : 0.01f * v3;
            }
            if (SPLITOUT) {
                u32* out = reinterpret_cast<u32*>(outv);
                if (r0 < M)
                    *reinterpret_cast<uint2*>(out + r0 * F + col) =
                        make_uint2(packsplit(v0), packsplit(v1));
                if (r0 + 8 < M)
                    *reinterpret_cast<uint2*>(out + (r0 + 8) * F + col) =
                        make_uint2(packsplit(v2), packsplit(v3));
            } else {
                float* out = reinterpret_cast<float*>(outv);
                if (r0 < M)
                    *reinterpret_cast<float2*>(out + r0 * F + col) = make_float2(v0, v1);
                if (r0 + 8 < M)
                    *reinterpret_cast<float2*>(out + (r0 + 8) * F + col) = make_float2(v2, v3);
            }
        }
    }
}

// ---------------- edge MLP in CSR order (one warp per dst node) ----------------
// B[dst], mw1 edge-weight column, mw2, mb2 loaded ONCE per node; per edge we
// only gather A[src] + efeat[eid] and write out[eid].
__global__ void __launch_bounds__(256) k_edge(
    const float* __restrict__ efeat, const float* __restrict__ mw1,
    const float* __restrict__ mw2, const float* __restrict__ mb2,
    float* __restrict__ out)
{
    int w    = (blockIdx.x * blockDim.x + threadIdx.x) >> 5;
    int lane = threadIdx.x & 31;
    if (w >= NNODES) return;
    int beg = g_rowptr[w], end = g_rowptr[w + 1];
    if (beg == end) return;
    int f0 = lane * 4;

    const float4 b  = *reinterpret_cast<const float4*>(g_B + w * F + f0);
    const float4 wr = *reinterpret_cast<const float4*>(mw1 + 256 * F + f0);
    const float4 q0 = *reinterpret_cast<const float4*>(mw2 + f0 * 2);
    const float4 q1 = *reinterpret_cast<const float4*>(mw2 + f0 * 2 + 4);
    const float c0 = mb2[0], c1 = mb2[1];

    for (int i = beg; i < end; i += 32) {
        int n = min(32, end - i);
        int sidx = 0, eidx = 0;
        float ev = 0.f;
        if (lane < n) {
            sidx = g_csrsrc[i + lane];
            eidx = g_csredge[i + lane];
            ev   = efeat[eidx];
        }
        float myp0 = 0.f, myp1 = 0.f;
        for (int j = 0; j < n; j++) {
            int   s = __shfl_sync(0xffffffffu, sidx, j);
            float e = __shfl_sync(0xffffffffu, ev, j);
            const float4 a = *reinterpret_cast<const float4*>(g_A + s * F + f0);
            float hx = fmaxf(fmaf(e, wr.x, a.x + b.x), 0.f);
            float hy = fmaxf(fmaf(e, wr.y, a.y + b.y), 0.f);
            float hz = fmaxf(fmaf(e, wr.z, a.z + b.z), 0.f);
            float hw = fmaxf(fmaf(e, wr.w, a.w + b.w), 0.f);
            float p0 = hx * q0.x + hy * q0.z + hz * q1.x + hw * q1.z;
            float p1 = hx * q0.y + hy * q0.w + hz * q1.y + hw * q1.w;
#pragma unroll
            for (int off = 16; off; off >>= 1) {
                p0 += __shfl_xor_sync(0xffffffffu, p0, off);
                p1 += __shfl_xor_sync(0xffffffffu, p1, off);
            }
            if (lane == j) { myp0 = p0; myp1 = p1; }
        }
        if (lane < n)
            *reinterpret_cast<float2*>(out + 2 * eidx) = make_float2(myp0 + c0, myp1 + c1);
    }
}

// ---------------- launch ----------------
extern "C" void kernel_launch(void* const* d_in, const int* in_sizes, int n_in,
                              void* d_out, int out_size) {
    const float* node = (const float*)d_in[0];
    const float* ef   = (const float*)d_in[1];
    const int*   src  = (const int*)d_in[2];
    const int*   dst  = (const int*)d_in[3];
    const float* ws0 = (const float*)d_in[4];
    const float* wn0 = (const float*)d_in[5];
    const float* b0  = (const float*)d_in[6];
    const float* ws1 = (const float*)d_in[7];
    const float* wn1 = (const float*)d_in[8];
    const float* b1  = (const float*)d_in[9];
    const float* ws2 = (const float*)d_in[10];
    const float* wn2 = (const float*)d_in[11];
    const float* b2  = (const float*)d_in[12];
    const float* mw1 = (const float*)d_in[13];
    const float* mb1 = (const float*)d_in[14];
    const float* mw2 = (const float*)d_in[15];
    const float* mb2 = (const float*)d_in[16];
    float* out = (float*)d_out;

    u32 *ns, *hs0, *hs1, *means, *wt;
    float *pA, *pB;
    cudaGetSymbolAddress((void**)&ns,    g_ns);
    cudaGetSymbolAddress((void**)&hs0,   g_hs0);
    cudaGetSymbolAddress((void**)&hs1,   g_hs1);
    cudaGetSymbolAddress((void**)&means, g_means);
    cudaGetSymbolAddress((void**)&wt,    g_wt);
    cudaGetSymbolAddress((void**)&pA,    g_A);
    cudaGetSymbolAddress((void**)&pB,    g_B);

    u32* wt_ws0 = wt + 0 * F * F;
    u32* wt_wn0 = wt + 1 * F * F;
    u32* wt_ws1 = wt + 2 * F * F;
    u32* wt_wn1 = wt + 3 * F * F;
    u32* wt_ws2 = wt + 4 * F * F;
    u32* wt_wn2 = wt + 5 * F * F;
    u32* wt_m1a = wt + 6 * F * F;
    u32* wt_m1b = wt + 7 * F * F;

    // one-time splits (node features + all 8 weight matrices in 2 launches)
    k_split<<<(NNODES * F + 255) / 256, 256>>>(node, ns, NNODES * F);
    WPtrs wp;
    wp.p[0] = ws0; wp.p[1] = wn0; wp.p[2] = ws1; wp.p[3] = wn1;
    wp.p[4] = ws2; wp.p[5] = wn2; wp.p[6] = mw1; wp.p[7] = mw1 + 128 * F;
    k_splitwt8<<<512, 256>>>(wp, wt);

    // CSR build (once, reused for all 3 layers + edge MLP)
    k_zero_deg<<<(NNODES + 255) / 256, 256>>>();
    k_hist<<<(NEDGES + 255) / 256, 256>>>(dst);
    k_scan1<<<NSCAN, SCAN_T>>>();
    k_scan2<<<1, 32>>>();
    k_scan3<<<(NNODES + 255) / 256, 256>>>();
    k_scatter<<<(NEDGES + 255) / 256, 256>>>(src, dst);

    const int aggBlocks  = (NNODES * 32 + 255) / 256;
    const int gemmBlocks = (NNODES + 127) / 128;

    // layer 0
    k_aggmean<<<aggBlocks, 256>>>(ns);
    gemm_tcs<true, true, true, false><<<gemmBlocks, 256>>>(
        ns, wt_ws0, means, wt_wn0, b0, hs0, nullptr, nullptr, NNODES);
    // layer 1
    k_aggmean<<<aggBlocks, 256>>>(hs0);
    gemm_tcs<true, true, true, false><<<gemmBlocks, 256>>>(
        hs0, wt_ws1, means, wt_wn1, b1, hs1, nullptr, nullptr, NNODES);
    // layer 2
    k_aggmean<<<aggBlocks, 256>>>(hs1);
    gemm_tcs<true, true, true, false><<<gemmBlocks, 256>>>(
        hs1, wt_ws2, means, wt_wn2, b2, hs0, nullptr, nullptr, NNODES);

    // factored edge MLP node precomputes, both in ONE launch (grid.y = 2):
    // y=0: A = h@mw1[0:128] + mb1 ; y=1: B = h@mw1[128:256]
    gemm_tcs<false, false, false, true><<<dim3(gemmBlocks, 2), 256>>>(
        hs0, wt_m1a, nullptr, nullptr, mb1, pA, wt_m1b, pB, NNODES);

    // edge MLP in CSR order
    k_edge<<<aggBlocks, 256>>>(ef, mw1, mw2, mb2, out);
}